// round 1
// baseline (speedup 1.0000x reference)
#include <cuda_runtime.h>
#include <cstdio>

#define NN   50000
#define NE   800000
#define FIN  256
#define FHID 256
#define FOUT 128

// ---------------- scratch (device globals; no dynamic allocation) ----------
__device__ int   g_deg[NN];
__device__ int   g_cur[NN];
__device__ float g_dinv[NN];
__device__ int   g_off[NN + 1];
__device__ int   g_csr[NE];
__device__ float g_T[(size_t)NN * FHID];   // x @ W1
__device__ float g_H[(size_t)NN * FHID];   // relu(Â T + b1)
__device__ float g_G[(size_t)NN * FHID];   // Â H

// ---------------- small graph-prep kernels ---------------------------------
__global__ void init_kernel() {
    int i = blockIdx.x * blockDim.x + threadIdx.x;
    if (i < NN) { g_deg[i] = 1; g_cur[i] = 0; }   // 1 = self-loop
}

__global__ void count_kernel(const int* __restrict__ dst) {
    int e = blockIdx.x * blockDim.x + threadIdx.x;
    if (e < NE) atomicAdd(&g_deg[dst[e]], 1);
}

__global__ void dinv_kernel() {
    int i = blockIdx.x * blockDim.x + threadIdx.x;
    if (i < NN) g_dinv[i] = rsqrtf((float)g_deg[i]);   // deg >= 1 always
}

// single-block prefix scan over edge-only counts (deg-1)
__global__ void scan_kernel() {
    __shared__ int partial[1024];
    const int t = threadIdx.x;
    const int CHUNK = (NN + 1023) / 1024;   // 49
    int lo = t * CHUNK;
    int hi = lo + CHUNK; if (hi > NN) hi = NN;
    int s = 0;
    for (int i = lo; i < hi; i++) s += g_deg[i] - 1;
    partial[t] = s;
    __syncthreads();
    for (int d = 1; d < 1024; d <<= 1) {
        int v = (t >= d) ? partial[t - d] : 0;
        __syncthreads();
        partial[t] += v;
        __syncthreads();
    }
    int run = (t == 0) ? 0 : partial[t - 1];
    for (int i = lo; i < hi; i++) {
        g_off[i] = run;
        run += g_deg[i] - 1;
    }
    if (t == 1023) g_off[NN] = partial[1023];
}

__global__ void fill_kernel(const int* __restrict__ src, const int* __restrict__ dst) {
    int e = blockIdx.x * blockDim.x + threadIdx.x;
    if (e < NE) {
        int d = dst[e];
        int pos = g_off[d] + atomicAdd(&g_cur[d], 1);
        g_csr[pos] = src[e];
    }
}

// ---------------- aggregation: warp per node, gather-side, no atomics ------
// out[i] = dinv[i] * ( dinv[i]*F[i] + sum_{s in N(i)} dinv[s]*F[s] )
// mode 0: out = relu(out + bias); mode 1: out as-is
__global__ void agg_kernel(const float* __restrict__ F, float* __restrict__ O,
                           const float* __restrict__ bias, int mode) {
    int gw = (blockIdx.x * blockDim.x + threadIdx.x) >> 5;
    if (gw >= NN) return;
    int lane = threadIdx.x & 31;

    float di = g_dinv[gw];
    const float4* sp = (const float4*)(F + (size_t)gw * FHID) + lane * 2;
    float4 v0 = sp[0], v1 = sp[1];
    float4 a0, a1;
    a0.x = di * v0.x; a0.y = di * v0.y; a0.z = di * v0.z; a0.w = di * v0.w;
    a1.x = di * v1.x; a1.y = di * v1.y; a1.z = di * v1.z; a1.w = di * v1.w;

    int e = g_off[gw], eend = g_off[gw + 1];
    for (; e < eend; e++) {
        int s = g_csr[e];
        float w = g_dinv[s];
        const float4* p = (const float4*)(F + (size_t)s * FHID) + lane * 2;
        float4 u0 = p[0], u1 = p[1];
        a0.x += w * u0.x; a0.y += w * u0.y; a0.z += w * u0.z; a0.w += w * u0.w;
        a1.x += w * u1.x; a1.y += w * u1.y; a1.z += w * u1.z; a1.w += w * u1.w;
    }
    a0.x *= di; a0.y *= di; a0.z *= di; a0.w *= di;
    a1.x *= di; a1.y *= di; a1.z *= di; a1.w *= di;

    if (mode == 0) {
        const float4* bp = (const float4*)bias + lane * 2;
        float4 b0 = bp[0], b1 = bp[1];
        a0.x = fmaxf(a0.x + b0.x, 0.f); a0.y = fmaxf(a0.y + b0.y, 0.f);
        a0.z = fmaxf(a0.z + b0.z, 0.f); a0.w = fmaxf(a0.w + b0.w, 0.f);
        a1.x = fmaxf(a1.x + b1.x, 0.f); a1.y = fmaxf(a1.y + b1.y, 0.f);
        a1.z = fmaxf(a1.z + b1.z, 0.f); a1.w = fmaxf(a1.w + b1.w, 0.f);
    }
    float4* op = (float4*)(O + (size_t)gw * FHID) + lane * 2;
    op[0] = a0; op[1] = a1;
}

// ---------------- SGEMM: C[M x ?] = A[M x 256] @ B[256 x ldb] (+ bias) -----
// 128x128 block tile, BK=16, 256 threads, 8x8 per-thread micro-tile.
#define BM 128
#define BN 128
#define BK 16

__global__ __launch_bounds__(256) void sgemm_kernel(
    const float* __restrict__ A, const float* __restrict__ B, int ldb,
    const float* __restrict__ bias,
    float* __restrict__ C, int ldc, int M) {
    __shared__ float As[BK][BM];
    __shared__ float Bs[BK][BN];

    const int t = threadIdx.x;
    const int tx = t & 15, ty = t >> 4;
    const int rowBase = blockIdx.x * BM;
    const int colBase = blockIdx.y * BN;

    float acc[8][8];
#pragma unroll
    for (int i = 0; i < 8; i++)
#pragma unroll
        for (int j = 0; j < 8; j++) acc[i][j] = 0.f;

    for (int k0 = 0; k0 < 256; k0 += BK) {
        // stage A tile (128 x 16) as As[k][row]
        {
            int id = t;
#pragma unroll
            for (int l = 0; l < 2; l++, id += 256) {
                int r = id >> 2;
                int c4 = (id & 3) << 2;
                int gr = rowBase + r;
                float4 v = make_float4(0.f, 0.f, 0.f, 0.f);
                if (gr < M) v = *(const float4*)(A + (size_t)gr * 256 + k0 + c4);
                As[c4 + 0][r] = v.x; As[c4 + 1][r] = v.y;
                As[c4 + 2][r] = v.z; As[c4 + 3][r] = v.w;
            }
        }
        // stage B tile (16 x 128)
        {
            int id = t;
#pragma unroll
            for (int l = 0; l < 2; l++, id += 256) {
                int kk = id >> 5;
                int c4 = (id & 31) << 2;
                float4 v = *(const float4*)(B + (size_t)(k0 + kk) * ldb + colBase + c4);
                *(float4*)&Bs[kk][c4] = v;
            }
        }
        __syncthreads();
#pragma unroll
        for (int kk = 0; kk < BK; kk++) {
            float4 a0 = *(const float4*)&As[kk][ty * 8];
            float4 a1 = *(const float4*)&As[kk][ty * 8 + 4];
            float4 b0 = *(const float4*)&Bs[kk][tx * 8];
            float4 b1 = *(const float4*)&Bs[kk][tx * 8 + 4];
            float av[8] = {a0.x, a0.y, a0.z, a0.w, a1.x, a1.y, a1.z, a1.w};
            float bv[8] = {b0.x, b0.y, b0.z, b0.w, b1.x, b1.y, b1.z, b1.w};
#pragma unroll
            for (int i = 0; i < 8; i++)
#pragma unroll
                for (int j = 0; j < 8; j++) acc[i][j] += av[i] * bv[j];
        }
        __syncthreads();
    }

    // epilogue
    float bcol[8];
#pragma unroll
    for (int j = 0; j < 8; j++)
        bcol[j] = bias ? bias[colBase + tx * 8 + j] : 0.f;

#pragma unroll
    for (int i = 0; i < 8; i++) {
        int gr = rowBase + ty * 8 + i;
        if (gr >= M) continue;
        float* crow = C + (size_t)gr * ldc + colBase + tx * 8;
        float4 o0, o1;
        o0.x = acc[i][0] + bcol[0]; o0.y = acc[i][1] + bcol[1];
        o0.z = acc[i][2] + bcol[2]; o0.w = acc[i][3] + bcol[3];
        o1.x = acc[i][4] + bcol[4]; o1.y = acc[i][5] + bcol[5];
        o1.z = acc[i][6] + bcol[6]; o1.w = acc[i][7] + bcol[7];
        *(float4*)(crow) = o0;
        *(float4*)(crow + 4) = o1;
    }
}

// ---------------- launch ----------------------------------------------------
extern "C" void kernel_launch(void* const* d_in, const int* in_sizes, int n_in,
                              void* d_out, int out_size) {
    const float* x    = (const float*)d_in[0];
    const int*   ei   = (const int*)d_in[1];   // [2, E]: row0 = src, row1 = dst
    const float* W1   = (const float*)d_in[2];
    const float* b1   = (const float*)d_in[3];
    const float* Wmu  = (const float*)d_in[4];
    const float* bmu  = (const float*)d_in[5];
    const float* Wls  = (const float*)d_in[6];
    const float* bls  = (const float*)d_in[7];
    float* out = (float*)d_out;

    const int* src = ei;
    const int* dst = ei + NE;

    float *pT, *pH, *pG;
    cudaGetSymbolAddress((void**)&pT, g_T);
    cudaGetSymbolAddress((void**)&pH, g_H);
    cudaGetSymbolAddress((void**)&pG, g_G);

    // graph prep
    init_kernel<<<(NN + 255) / 256, 256>>>();
    count_kernel<<<(NE + 255) / 256, 256>>>(dst);
    dinv_kernel<<<(NN + 255) / 256, 256>>>();
    scan_kernel<<<1, 1024>>>();
    fill_kernel<<<(NE + 255) / 256, 256>>>(src, dst);

    // layer 1: T = x @ W1
    {
        dim3 grid((NN + BM - 1) / BM, FHID / BN);
        sgemm_kernel<<<grid, 256>>>(x, W1, FHID, nullptr, pT, FHID, NN);
    }
    // H = relu(Â T + b1)
    agg_kernel<<<(NN * 32 + 255) / 256, 256>>>(pT, pH, b1, 0);
    // G = Â H   (aggregation commutes with linear transform: Â(hW) = (Âh)W)
    agg_kernel<<<(NN * 32 + 255) / 256, 256>>>(pH, pG, nullptr, 1);

    // mu = G @ Wmu + bmu ; ls = G @ Wls + bls  (output: [mu ; ls] concat)
    {
        dim3 grid((NN + BM - 1) / BM, 1);
        sgemm_kernel<<<grid, 256>>>(pG, Wmu, FOUT, bmu, out, FOUT, NN);
        sgemm_kernel<<<grid, 256>>>(pG, Wls, FOUT, bls, out + (size_t)NN * FOUT, FOUT, NN);
    }
}

// round 2
// speedup vs baseline: 2.0172x; 2.0172x over previous
#include <cuda_runtime.h>
#include <cstdint>

#define NN   50000
#define NE   800000
#define FHID 256
#define FOUT 128
#define NB   ((NN + 255) / 256)   // 196 blocks for scan

// ---------------- scratch (device globals; no dynamic allocation) ----------
__device__ int   g_deg[NN];
__device__ int   g_cur[NN];
__device__ float g_dinv[NN];
__device__ int   g_off[NN + 1];
__device__ int   g_csr[NE];
__device__ int   g_bsum[NB];
__device__ int   g_boff[NB];
__device__ float g_T[(size_t)NN * FHID];   // x @ W1
__device__ float g_H[(size_t)NN * FHID];   // relu(Â T + b1)
__device__ float g_G[(size_t)NN * FHID];   // Â H

// ---------------- small graph-prep kernels ---------------------------------
__global__ void init_kernel() {
    int i = blockIdx.x * blockDim.x + threadIdx.x;
    if (i < NN) { g_deg[i] = 1; g_cur[i] = 0; }   // 1 = self-loop
}

__global__ void count_kernel(const int* __restrict__ dst) {
    int e = blockIdx.x * blockDim.x + threadIdx.x;
    if (e < NE) atomicAdd(&g_deg[dst[e]], 1);
}

__global__ void dinv_kernel() {
    int i = blockIdx.x * blockDim.x + threadIdx.x;
    if (i < NN) g_dinv[i] = rsqrtf((float)g_deg[i]);   // deg >= 1 always
}

// --- multi-block exclusive scan of (deg-1), 3 tiny kernels ---
__global__ void blocksum_kernel() {
    int i = blockIdx.x * 256 + threadIdx.x;
    int v = (i < NN) ? g_deg[i] - 1 : 0;
#pragma unroll
    for (int o = 16; o; o >>= 1) v += __shfl_down_sync(0xffffffffu, v, o);
    __shared__ int ws[8];
    if ((threadIdx.x & 31) == 0) ws[threadIdx.x >> 5] = v;
    __syncthreads();
    if (threadIdx.x < 8) {
        int s = ws[threadIdx.x];
#pragma unroll
        for (int o = 4; o; o >>= 1) s += __shfl_down_sync(0xffu, s, o);
        if (threadIdx.x == 0) g_bsum[blockIdx.x] = s;
    }
}

__global__ void bscan_kernel() {   // one block, 256 threads, scans NB partials
    __shared__ int sh[256];
    int t = threadIdx.x;
    int v = (t < NB) ? g_bsum[t] : 0;
    sh[t] = v; __syncthreads();
    for (int o = 1; o < 256; o <<= 1) {
        int u = (t >= o) ? sh[t - o] : 0;
        __syncthreads();
        sh[t] += u;
        __syncthreads();
    }
    if (t < NB) g_boff[t] = sh[t] - v;   // exclusive
}

__global__ void offsets_kernel() {
    __shared__ int sh[256];
    int b = blockIdx.x, t = threadIdx.x;
    int i = b * 256 + t;
    int v = (i < NN) ? g_deg[i] - 1 : 0;
    sh[t] = v; __syncthreads();
    for (int o = 1; o < 256; o <<= 1) {
        int u = (t >= o) ? sh[t - o] : 0;
        __syncthreads();
        sh[t] += u;
        __syncthreads();
    }
    int excl = sh[t] - v + g_boff[b];
    if (i < NN)      g_off[i]  = excl;
    if (i == NN - 1) g_off[NN] = excl + v;
}

__global__ void fill_kernel(const int* __restrict__ src, const int* __restrict__ dst) {
    int e = blockIdx.x * blockDim.x + threadIdx.x;
    if (e < NE) {
        int d = dst[e];
        int pos = g_off[d] + atomicAdd(&g_cur[d], 1);
        g_csr[pos] = src[e];
    }
}

// ---------------- aggregation: warp per node, gather-side, no atomics ------
__global__ void agg_kernel(const float* __restrict__ F, float* __restrict__ O,
                           const float* __restrict__ bias, int mode) {
    int gw = (blockIdx.x * blockDim.x + threadIdx.x) >> 5;
    if (gw >= NN) return;
    int lane = threadIdx.x & 31;

    float di = g_dinv[gw];
    const float4* sp = (const float4*)(F + (size_t)gw * FHID) + lane * 2;
    float4 v0 = sp[0], v1 = sp[1];
    float4 a0, a1;
    a0.x = di * v0.x; a0.y = di * v0.y; a0.z = di * v0.z; a0.w = di * v0.w;
    a1.x = di * v1.x; a1.y = di * v1.y; a1.z = di * v1.z; a1.w = di * v1.w;

    int e = g_off[gw], eend = g_off[gw + 1];
    for (; e < eend; e++) {
        int s = g_csr[e];
        float w = g_dinv[s];
        const float4* p = (const float4*)(F + (size_t)s * FHID) + lane * 2;
        float4 u0 = p[0], u1 = p[1];
        a0.x += w * u0.x; a0.y += w * u0.y; a0.z += w * u0.z; a0.w += w * u0.w;
        a1.x += w * u1.x; a1.y += w * u1.y; a1.z += w * u1.z; a1.w += w * u1.w;
    }
    a0.x *= di; a0.y *= di; a0.z *= di; a0.w *= di;
    a1.x *= di; a1.y *= di; a1.z *= di; a1.w *= di;

    if (mode == 0) {
        const float4* bp = (const float4*)bias + lane * 2;
        float4 b0 = bp[0], b1 = bp[1];
        a0.x = fmaxf(a0.x + b0.x, 0.f); a0.y = fmaxf(a0.y + b0.y, 0.f);
        a0.z = fmaxf(a0.z + b0.z, 0.f); a0.w = fmaxf(a0.w + b0.w, 0.f);
        a1.x = fmaxf(a1.x + b1.x, 0.f); a1.y = fmaxf(a1.y + b1.y, 0.f);
        a1.z = fmaxf(a1.z + b1.z, 0.f); a1.w = fmaxf(a1.w + b1.w, 0.f);
    }
    float4* op = (float4*)(O + (size_t)gw * FHID) + lane * 2;
    op[0] = a0; op[1] = a1;
}

// ---------------- TF32 tensor-core GEMM ------------------------------------
// C[M x N] = A[M x 256] @ B[256 x N] (+ bias), A/B row-major fp32.
// 128x128 block tile, BK=32, 256 threads = 8 warps in 2(m) x 4(n),
// warp tile 64x32 via mma.sync.m16n8k8.tf32 (4 m-tiles x 4 n-tiles x 4 k-steps).
__device__ __forceinline__ uint32_t f2tf32(float f) {
    uint32_t o;
    asm("cvt.rna.tf32.f32 %0, %1;" : "=r"(o) : "f"(f));
    return o;
}

__device__ __forceinline__ void mma_tf32(float* d, const uint32_t* a, const uint32_t* b) {
    asm volatile(
        "mma.sync.aligned.m16n8k8.row.col.f32.tf32.tf32.f32 "
        "{%0,%1,%2,%3}, {%4,%5,%6,%7}, {%8,%9}, {%0,%1,%2,%3};"
        : "+f"(d[0]), "+f"(d[1]), "+f"(d[2]), "+f"(d[3])
        : "r"(a[0]), "r"(a[1]), "r"(a[2]), "r"(a[3]), "r"(b[0]), "r"(b[1]));
}

#define GBM 128
#define GBN 128
#define GBK 32

__global__ __launch_bounds__(256) void tf32gemm_kernel(
    const float* __restrict__ A, const float* __restrict__ B, int ldb,
    const float* __restrict__ bias,
    float* __restrict__ C, int ldc, int M) {
    __shared__ uint32_t As[GBM][GBK + 4];   // stride 36 words: frag loads conflict-free
    __shared__ uint32_t Bs[GBK][GBN + 8];   // stride 136 words: frag loads conflict-free

    const int t = threadIdx.x;
    const int lane = t & 31;
    const int warp = t >> 5;
    const int warpM = warp >> 2;       // 0..1
    const int warpN = warp & 3;        // 0..3
    const int l4 = lane >> 2, k4 = lane & 3;
    const int rowBase = blockIdx.x * GBM;
    const int colBase = blockIdx.y * GBN;
    const int mBase = warpM * 64;
    const int nBase = warpN * 32;

    float acc[4][4][4];
#pragma unroll
    for (int i = 0; i < 4; i++)
#pragma unroll
        for (int j = 0; j < 4; j++)
#pragma unroll
            for (int r = 0; r < 4; r++) acc[i][j][r] = 0.f;

    for (int k0 = 0; k0 < 256; k0 += GBK) {
        // stage A tile (128 x 32): 256 thr x 4 float4
#pragma unroll
        for (int l = 0; l < 4; l++) {
            int s = l * 256 + t;
            int row = s >> 3;
            int c4 = (s & 7) << 2;
            int gr = rowBase + row;
            float4 v = make_float4(0.f, 0.f, 0.f, 0.f);
            if (gr < M) v = *(const float4*)(A + (size_t)gr * 256 + k0 + c4);
            uint4 u;
            u.x = f2tf32(v.x); u.y = f2tf32(v.y); u.z = f2tf32(v.z); u.w = f2tf32(v.w);
            *(uint4*)&As[row][c4] = u;
        }
        // stage B tile (32 x 128)
#pragma unroll
        for (int l = 0; l < 4; l++) {
            int s = l * 256 + t;
            int kk = s >> 5;
            int c4 = (s & 31) << 2;
            float4 v = *(const float4*)(B + (size_t)(k0 + kk) * ldb + colBase + c4);
            uint4 u;
            u.x = f2tf32(v.x); u.y = f2tf32(v.y); u.z = f2tf32(v.z); u.w = f2tf32(v.w);
            *(uint4*)&Bs[kk][c4] = u;
        }
        __syncthreads();

#pragma unroll
        for (int kk = 0; kk < GBK; kk += 8) {
            uint32_t af[4][4], bf[4][2];
#pragma unroll
            for (int mi = 0; mi < 4; mi++) {
                int r = mBase + mi * 16 + l4;
                af[mi][0] = As[r][kk + k4];
                af[mi][1] = As[r + 8][kk + k4];
                af[mi][2] = As[r][kk + k4 + 4];
                af[mi][3] = As[r + 8][kk + k4 + 4];
            }
#pragma unroll
            for (int ni = 0; ni < 4; ni++) {
                int n = nBase + ni * 8 + l4;
                bf[ni][0] = Bs[kk + k4][n];
                bf[ni][1] = Bs[kk + k4 + 4][n];
            }
#pragma unroll
            for (int mi = 0; mi < 4; mi++)
#pragma unroll
                for (int ni = 0; ni < 4; ni++)
                    mma_tf32(acc[mi][ni], af[mi], bf[ni]);
        }
        __syncthreads();
    }

    // epilogue
#pragma unroll
    for (int mi = 0; mi < 4; mi++) {
        int r0 = rowBase + mBase + mi * 16 + l4;
        int r1 = r0 + 8;
#pragma unroll
        for (int ni = 0; ni < 4; ni++) {
            int c = colBase + nBase + ni * 8 + k4 * 2;
            float bv0 = bias ? bias[c] : 0.f;
            float bv1 = bias ? bias[c + 1] : 0.f;
            if (r0 < M) {
                float2 o; o.x = acc[mi][ni][0] + bv0; o.y = acc[mi][ni][1] + bv1;
                *(float2*)(C + (size_t)r0 * ldc + c) = o;
            }
            if (r1 < M) {
                float2 o; o.x = acc[mi][ni][2] + bv0; o.y = acc[mi][ni][3] + bv1;
                *(float2*)(C + (size_t)r1 * ldc + c) = o;
            }
        }
    }
}

// ---------------- launch ----------------------------------------------------
extern "C" void kernel_launch(void* const* d_in, const int* in_sizes, int n_in,
                              void* d_out, int out_size) {
    const float* x    = (const float*)d_in[0];
    const int*   ei   = (const int*)d_in[1];   // [2, E]: row0 = src, row1 = dst
    const float* W1   = (const float*)d_in[2];
    const float* b1   = (const float*)d_in[3];
    const float* Wmu  = (const float*)d_in[4];
    const float* bmu  = (const float*)d_in[5];
    const float* Wls  = (const float*)d_in[6];
    const float* bls  = (const float*)d_in[7];
    float* out = (float*)d_out;

    const int* src = ei;
    const int* dst = ei + NE;

    float *pT, *pH, *pG;
    cudaGetSymbolAddress((void**)&pT, g_T);
    cudaGetSymbolAddress((void**)&pH, g_H);
    cudaGetSymbolAddress((void**)&pG, g_G);

    // graph prep
    init_kernel<<<(NN + 255) / 256, 256>>>();
    count_kernel<<<(NE + 255) / 256, 256>>>(dst);
    dinv_kernel<<<(NN + 255) / 256, 256>>>();
    blocksum_kernel<<<NB, 256>>>();
    bscan_kernel<<<1, 256>>>();
    offsets_kernel<<<NB, 256>>>();
    fill_kernel<<<(NE + 255) / 256, 256>>>(src, dst);

    // layer 1: T = x @ W1   (tf32 tensor cores)
    {
        dim3 grid((NN + GBM - 1) / GBM, FHID / GBN);
        tf32gemm_kernel<<<grid, 256>>>(x, W1, FHID, nullptr, pT, FHID, NN);
    }
    // H = relu(Â T + b1)
    agg_kernel<<<(NN * 32 + 255) / 256, 256>>>(pT, pH, b1, 0);
    // G = Â H   (aggregation commutes with the dense transform)
    agg_kernel<<<(NN * 32 + 255) / 256, 256>>>(pH, pG, nullptr, 1);

    // mu = G @ Wmu + bmu ; ls = G @ Wls + bls  (output: [mu ; ls] concat)
    {
        dim3 grid((NN + GBM - 1) / GBM, 1);
        tf32gemm_kernel<<<grid, 256>>>(pG, Wmu, FOUT, bmu, out, FOUT, NN);
        tf32gemm_kernel<<<grid, 256>>>(pG, Wls, FOUT, bls, out + (size_t)NN * FOUT, FOUT, NN);
    }
}

// round 3
// speedup vs baseline: 2.8504x; 1.4131x over previous
#include <cuda_runtime.h>
#include <cuda_fp16.h>
#include <cstdint>

#define NN   50000
#define NE   800000
#define FHID 256
#define FOUT 128
#define NB   ((NN + 255) / 256)

// ---------------- scratch (device globals; no dynamic allocation) ----------
__device__ int     g_deg[NN];
__device__ int     g_cur[NN];
__device__ float   g_dinv[NN];
__device__ int     g_off[NN + 1];
__device__ int     g_csr[NE];
__device__ int     g_bsum[NB];
__device__ int     g_boff[NB];
__device__ __half2 g_T[(size_t)NN * 128];   // x @ W1            (fp16)
__device__ __half2 g_H[(size_t)NN * 128];   // relu(Â T + b1)    (fp16)
__device__ float   g_G[(size_t)NN * 256];   // Â H               (fp32)
__device__ float   g_Wcat[256 * 256];       // [Wmu | Wls]
__device__ float   g_bcat[256];

// ---------------- graph prep -----------------------------------------------
__global__ void init_kernel() {
    int i = blockIdx.x * blockDim.x + threadIdx.x;
    if (i < NN) { g_deg[i] = 1; g_cur[i] = 0; }
}
__global__ void count_kernel(const int* __restrict__ dst) {
    int e = blockIdx.x * blockDim.x + threadIdx.x;
    if (e < NE) atomicAdd(&g_deg[dst[e]], 1);
}
__global__ void dinv_kernel() {
    int i = blockIdx.x * blockDim.x + threadIdx.x;
    if (i < NN) g_dinv[i] = rsqrtf((float)g_deg[i]);
}
__global__ void blocksum_kernel() {
    int i = blockIdx.x * 256 + threadIdx.x;
    int v = (i < NN) ? g_deg[i] - 1 : 0;
#pragma unroll
    for (int o = 16; o; o >>= 1) v += __shfl_down_sync(0xffffffffu, v, o);
    __shared__ int ws[8];
    if ((threadIdx.x & 31) == 0) ws[threadIdx.x >> 5] = v;
    __syncthreads();
    if (threadIdx.x < 8) {
        int s = ws[threadIdx.x];
#pragma unroll
        for (int o = 4; o; o >>= 1) s += __shfl_down_sync(0xffu, s, o);
        if (threadIdx.x == 0) g_bsum[blockIdx.x] = s;
    }
}
__global__ void bscan_kernel() {
    __shared__ int sh[256];
    int t = threadIdx.x;
    int v = (t < NB) ? g_bsum[t] : 0;
    sh[t] = v; __syncthreads();
    for (int o = 1; o < 256; o <<= 1) {
        int u = (t >= o) ? sh[t - o] : 0;
        __syncthreads(); sh[t] += u; __syncthreads();
    }
    if (t < NB) g_boff[t] = sh[t] - v;
}
__global__ void offsets_kernel() {
    __shared__ int sh[256];
    int b = blockIdx.x, t = threadIdx.x;
    int i = b * 256 + t;
    int v = (i < NN) ? g_deg[i] - 1 : 0;
    sh[t] = v; __syncthreads();
    for (int o = 1; o < 256; o <<= 1) {
        int u = (t >= o) ? sh[t - o] : 0;
        __syncthreads(); sh[t] += u; __syncthreads();
    }
    int excl = sh[t] - v + g_boff[b];
    if (i < NN)      g_off[i]  = excl;
    if (i == NN - 1) g_off[NN] = excl + v;
}
__global__ void fill_kernel(const int* __restrict__ src, const int* __restrict__ dst) {
    int e = blockIdx.x * blockDim.x + threadIdx.x;
    if (e < NE) {
        int d = dst[e];
        int pos = g_off[d] + atomicAdd(&g_cur[d], 1);
        g_csr[pos] = src[e];
    }
}
__global__ void wcat_kernel(const float* __restrict__ Wmu, const float* __restrict__ Wls,
                            const float* __restrict__ bmu, const float* __restrict__ bls) {
    int i = blockIdx.x * 256 + threadIdx.x;   // i over 256*256
    int k = i >> 8, c = i & 255;
    g_Wcat[i] = (c < 128) ? Wmu[k * 128 + c] : Wls[k * 128 + (c - 128)];
    if (i < 256) g_bcat[i] = (i < 128) ? bmu[i] : bls[i - 128];
}

// ---------------- aggregation (fp16 gather, fp32 accumulate) ---------------
// OUT_HALF=1: O is __half2 rows, add bias + relu. OUT_HALF=0: O is float rows.
template <int OUT_HALF>
__global__ void agg_h(const __half2* __restrict__ F, void* __restrict__ O,
                      const float* __restrict__ bias) {
    int gw = (blockIdx.x * blockDim.x + threadIdx.x) >> 5;
    if (gw >= NN) return;
    int lane = threadIdx.x & 31;

    float di = g_dinv[gw];
    float a[8];
    {
        uint4 v = *((const uint4*)(F + (size_t)gw * 128) + lane);
        const __half2* h = (const __half2*)&v;
#pragma unroll
        for (int j = 0; j < 4; j++) {
            float2 f = __half22float2(h[j]);
            a[2 * j]     = di * f.x;
            a[2 * j + 1] = di * f.y;
        }
    }
    int e = g_off[gw], eend = g_off[gw + 1];
#pragma unroll 2
    for (; e < eend; e++) {
        int s = g_csr[e];
        float w = g_dinv[s];
        uint4 v = *((const uint4*)(F + (size_t)s * 128) + lane);
        const __half2* h = (const __half2*)&v;
#pragma unroll
        for (int j = 0; j < 4; j++) {
            float2 f = __half22float2(h[j]);
            a[2 * j]     += w * f.x;
            a[2 * j + 1] += w * f.y;
        }
    }
#pragma unroll
    for (int j = 0; j < 8; j++) a[j] *= di;

    if (OUT_HALF) {
        const float4* bp = (const float4*)bias + lane * 2;
        float4 b0 = bp[0], b1 = bp[1];
        float bb[8] = {b0.x, b0.y, b0.z, b0.w, b1.x, b1.y, b1.z, b1.w};
        uint4 o;
        __half2* oh = (__half2*)&o;
#pragma unroll
        for (int j = 0; j < 4; j++) {
            float x0 = fmaxf(a[2 * j]     + bb[2 * j],     0.f);
            float x1 = fmaxf(a[2 * j + 1] + bb[2 * j + 1], 0.f);
            oh[j] = __floats2half2_rn(x0, x1);
        }
        *((uint4*)O + (size_t)gw * 32 + lane) = o;
    } else {
        float* op = (float*)O + (size_t)gw * 256 + lane * 8;
        *(float4*)op       = make_float4(a[0], a[1], a[2], a[3]);
        *(float4*)(op + 4) = make_float4(a[4], a[5], a[6], a[7]);
    }
}

// ---------------- TF32 tensor-core GEMM with register prefetch -------------
// C = A[M x 256] @ B[256 x 256] (+bias). Grid (ceil(M/128), 2).
// MODE 0: write fp16 to C (ld 256 halfs), no bias.
// MODE 1: write fp32 routed: blockIdx.y==0 -> Cout, ==1 -> Cout + NN*128 (ld 128).
__device__ __forceinline__ uint32_t f2tf32(float f) {
    uint32_t o;
    asm("cvt.rna.tf32.f32 %0, %1;" : "=r"(o) : "f"(f));
    return o;
}
__device__ __forceinline__ void mma_tf32(float* d, const uint32_t* a, const uint32_t* b) {
    asm volatile(
        "mma.sync.aligned.m16n8k8.row.col.f32.tf32.tf32.f32 "
        "{%0,%1,%2,%3}, {%4,%5,%6,%7}, {%8,%9}, {%0,%1,%2,%3};"
        : "+f"(d[0]), "+f"(d[1]), "+f"(d[2]), "+f"(d[3])
        : "r"(a[0]), "r"(a[1]), "r"(a[2]), "r"(a[3]), "r"(b[0]), "r"(b[1]));
}

#define GBM 128
#define GBK 32

template <int MODE>
__global__ __launch_bounds__(256) void tf32gemm_kernel(
    const float* __restrict__ A, const float* __restrict__ B,
    const float* __restrict__ bias, void* __restrict__ Cout, int M) {
    __shared__ uint32_t As[GBM][GBK + 4];   // stride 36 words
    __shared__ uint32_t Bs[GBK][128 + 8];   // stride 136 words

    const int t = threadIdx.x;
    const int lane = t & 31;
    const int warp = t >> 5;
    const int warpM = warp >> 2;
    const int warpN = warp & 3;
    const int l4 = lane >> 2, k4 = lane & 3;
    const int rowBase = blockIdx.x * GBM;
    const int colBase = blockIdx.y * 128;
    const int mBase = warpM * 64;
    const int nBase = warpN * 32;

    // staging coordinates (constant across tiles)
    const int aRow = t >> 3;           // +0,+32,+64,+96 over 4 chunks
    const int aC4  = (t & 7) << 2;
    const int bKk  = t >> 5;           // +0,+8,+16,+24
    const int bC4  = (t & 31) << 2;

    float4 ra[4], rb[4];
#pragma unroll
    for (int l = 0; l < 4; l++) {
        int gr = rowBase + aRow + l * 32;
        ra[l] = (gr < M) ? *(const float4*)(A + (size_t)gr * 256 + aC4)
                         : make_float4(0.f, 0.f, 0.f, 0.f);
        rb[l] = *(const float4*)(B + (size_t)(bKk + l * 8) * 256 + colBase + bC4);
    }

    float acc[4][4][4];
#pragma unroll
    for (int i = 0; i < 4; i++)
#pragma unroll
        for (int j = 0; j < 4; j++)
#pragma unroll
            for (int r = 0; r < 4; r++) acc[i][j][r] = 0.f;

    for (int it = 0; it < 8; it++) {
        // store prefetched regs -> smem (with tf32 convert)
#pragma unroll
        for (int l = 0; l < 4; l++) {
            uint4 ua, ub;
            ua.x = f2tf32(ra[l].x); ua.y = f2tf32(ra[l].y);
            ua.z = f2tf32(ra[l].z); ua.w = f2tf32(ra[l].w);
            ub.x = f2tf32(rb[l].x); ub.y = f2tf32(rb[l].y);
            ub.z = f2tf32(rb[l].z); ub.w = f2tf32(rb[l].w);
            *(uint4*)&As[aRow + l * 32][aC4] = ua;
            *(uint4*)&Bs[bKk + l * 8][bC4]  = ub;
        }
        __syncthreads();

        // issue next tile's global loads (overlaps the MMA work below)
        if (it < 7) {
            int k0 = (it + 1) * GBK;
#pragma unroll
            for (int l = 0; l < 4; l++) {
                int gr = rowBase + aRow + l * 32;
                ra[l] = (gr < M) ? *(const float4*)(A + (size_t)gr * 256 + k0 + aC4)
                                 : make_float4(0.f, 0.f, 0.f, 0.f);
                rb[l] = *(const float4*)(B + (size_t)(k0 + bKk + l * 8) * 256 + colBase + bC4);
            }
        }

#pragma unroll
        for (int kk = 0; kk < GBK; kk += 8) {
            uint32_t af[4][4], bf[4][2];
#pragma unroll
            for (int mi = 0; mi < 4; mi++) {
                int r = mBase + mi * 16 + l4;
                af[mi][0] = As[r][kk + k4];
                af[mi][1] = As[r + 8][kk + k4];
                af[mi][2] = As[r][kk + k4 + 4];
                af[mi][3] = As[r + 8][kk + k4 + 4];
            }
#pragma unroll
            for (int ni = 0; ni < 4; ni++) {
                int n = nBase + ni * 8 + l4;
                bf[ni][0] = Bs[kk + k4][n];
                bf[ni][1] = Bs[kk + k4 + 4][n];
            }
#pragma unroll
            for (int mi = 0; mi < 4; mi++)
#pragma unroll
                for (int ni = 0; ni < 4; ni++)
                    mma_tf32(acc[mi][ni], af[mi], bf[ni]);
        }
        __syncthreads();
    }

    // epilogue
#pragma unroll
    for (int mi = 0; mi < 4; mi++) {
        int r0 = rowBase + mBase + mi * 16 + l4;
        int r1 = r0 + 8;
#pragma unroll
        for (int ni = 0; ni < 4; ni++) {
            int cl = nBase + ni * 8 + k4 * 2;       // column within 128-tile
            if (MODE == 0) {
                __half2* T = (__half2*)Cout;
                int c = colBase + cl;               // 0..255
                if (r0 < M) T[(size_t)r0 * 128 + (c >> 1)] =
                    __floats2half2_rn(acc[mi][ni][0], acc[mi][ni][1]);
                if (r1 < M) T[(size_t)r1 * 128 + (c >> 1)] =
                    __floats2half2_rn(acc[mi][ni][2], acc[mi][ni][3]);
            } else {
                float* Co = (float*)Cout + (blockIdx.y ? (size_t)NN * 128 : 0);
                float bv0 = bias[colBase + cl];
                float bv1 = bias[colBase + cl + 1];
                if (r0 < M) {
                    float2 o; o.x = acc[mi][ni][0] + bv0; o.y = acc[mi][ni][1] + bv1;
                    *(float2*)(Co + (size_t)r0 * 128 + cl) = o;
                }
                if (r1 < M) {
                    float2 o; o.x = acc[mi][ni][2] + bv0; o.y = acc[mi][ni][3] + bv1;
                    *(float2*)(Co + (size_t)r1 * 128 + cl) = o;
                }
            }
        }
    }
}

// ---------------- launch ----------------------------------------------------
extern "C" void kernel_launch(void* const* d_in, const int* in_sizes, int n_in,
                              void* d_out, int out_size) {
    const float* x    = (const float*)d_in[0];
    const int*   ei   = (const int*)d_in[1];
    const float* W1   = (const float*)d_in[2];
    const float* b1   = (const float*)d_in[3];
    const float* Wmu  = (const float*)d_in[4];
    const float* bmu  = (const float*)d_in[5];
    const float* Wls  = (const float*)d_in[6];
    const float* bls  = (const float*)d_in[7];
    float* out = (float*)d_out;

    const int* src = ei;
    const int* dst = ei + NE;

    __half2 *pT, *pH; float *pG, *pWcat, *pbcat;
    cudaGetSymbolAddress((void**)&pT, g_T);
    cudaGetSymbolAddress((void**)&pH, g_H);
    cudaGetSymbolAddress((void**)&pG, g_G);
    cudaGetSymbolAddress((void**)&pWcat, g_Wcat);
    cudaGetSymbolAddress((void**)&pbcat, g_bcat);

    // graph prep + weight concat
    init_kernel<<<(NN + 255) / 256, 256>>>();
    count_kernel<<<(NE + 255) / 256, 256>>>(dst);
    wcat_kernel<<<256, 256>>>(Wmu, Wls, bmu, bls);
    dinv_kernel<<<(NN + 255) / 256, 256>>>();
    blocksum_kernel<<<NB, 256>>>();
    bscan_kernel<<<1, 256>>>();
    offsets_kernel<<<NB, 256>>>();
    fill_kernel<<<(NE + 255) / 256, 256>>>(src, dst);

    dim3 ggrid((NN + GBM - 1) / GBM, 2);
    // T = x @ W1  (fp16 out)
    tf32gemm_kernel<0><<<ggrid, 256>>>(x, W1, nullptr, pT, NN);
    // H = relu(Â T + b1)  (fp16 -> fp16)
    agg_h<1><<<(NN * 32 + 255) / 256, 256>>>(pT, pH, b1);
    // G = Â H  (fp16 -> fp32)
    agg_h<0><<<(NN * 32 + 255) / 256, 256>>>(pH, pG, nullptr);
    // [mu | ls] = G @ [Wmu | Wls] + [bmu | bls]
    tf32gemm_kernel<1><<<ggrid, 256>>>(pG, pWcat, pbcat, out, NN);
}

// round 5
// speedup vs baseline: 3.3258x; 1.1668x over previous
#include <cuda_runtime.h>
#include <cuda_fp16.h>
#include <cstdint>

#define NN   50000
#define NE   800000
#define NB   ((NN + 255) / 256)

// ---------------- scratch (device globals; no dynamic allocation) ----------
__device__ int     g_deg[NN];
__device__ int     g_cur[NN];
__device__ float   g_dinv[NN];
__device__ int     g_off[NN + 1];
__device__ int     g_csr[NE];
__device__ int     g_bsum[NB];
__device__ int     g_boff[NB];
__device__ __half2 g_T[(size_t)NN * 128];   // x @ W1            (fp16)
__device__ __half2 g_H[(size_t)NN * 128];   // relu(Â T + b1)    (fp16)
__device__ __half2 g_G[(size_t)NN * 128];   // Â H               (fp16)
__device__ float   g_Wcat[256 * 256];       // [Wmu | Wls]
__device__ float   g_bcat[256];

__device__ __forceinline__ uint32_t h2u(__half2 h) {
    return *reinterpret_cast<uint32_t*>(&h);
}

// ---------------- graph prep -----------------------------------------------
__global__ void init_kernel() {
    int i = blockIdx.x * blockDim.x + threadIdx.x;
    if (i < NN) { g_deg[i] = 1; g_cur[i] = 0; }
}
__global__ void count_kernel(const int* __restrict__ dst) {
    int e = blockIdx.x * blockDim.x + threadIdx.x;
    if (e < NE) atomicAdd(&g_deg[dst[e]], 1);
}
// fused: dinv + per-block degree sums
__global__ void blocksum_kernel() {
    int i = blockIdx.x * 256 + threadIdx.x;
    int d = (i < NN) ? g_deg[i] : 1;
    if (i < NN) g_dinv[i] = rsqrtf((float)d);
    int v = (i < NN) ? d - 1 : 0;
#pragma unroll
    for (int o = 16; o; o >>= 1) v += __shfl_down_sync(0xffffffffu, v, o);
    __shared__ int ws[8];
    if ((threadIdx.x & 31) == 0) ws[threadIdx.x >> 5] = v;
    __syncthreads();
    if (threadIdx.x < 8) {
        int s = ws[threadIdx.x];
#pragma unroll
        for (int o = 4; o; o >>= 1) s += __shfl_down_sync(0xffu, s, o);
        if (threadIdx.x == 0) g_bsum[blockIdx.x] = s;
    }
}
__global__ void bscan_kernel() {
    __shared__ int sh[256];
    int t = threadIdx.x;
    int v = (t < NB) ? g_bsum[t] : 0;
    sh[t] = v; __syncthreads();
    for (int o = 1; o < 256; o <<= 1) {
        int u = (t >= o) ? sh[t - o] : 0;
        __syncthreads(); sh[t] += u; __syncthreads();
    }
    if (t < NB) g_boff[t] = sh[t] - v;
}
__global__ void offsets_kernel() {
    __shared__ int sh[256];
    int b = blockIdx.x, t = threadIdx.x;
    int i = b * 256 + t;
    int v = (i < NN) ? g_deg[i] - 1 : 0;
    sh[t] = v; __syncthreads();
    for (int o = 1; o < 256; o <<= 1) {
        int u = (t >= o) ? sh[t - o] : 0;
        __syncthreads(); sh[t] += u; __syncthreads();
    }
    int excl = sh[t] - v + g_boff[b];
    if (i < NN)      g_off[i]  = excl;
    if (i == NN - 1) g_off[NN] = excl + v;
}
__global__ void fill_kernel(const int* __restrict__ src, const int* __restrict__ dst) {
    int e = blockIdx.x * blockDim.x + threadIdx.x;
    if (e < NE) {
        int d = dst[e];
        int pos = g_off[d] + atomicAdd(&g_cur[d], 1);
        g_csr[pos] = src[e];
    }
}
__global__ void wcat_kernel(const float* __restrict__ Wmu, const float* __restrict__ Wls,
                            const float* __restrict__ bmu, const float* __restrict__ bls) {
    int i = blockIdx.x * 256 + threadIdx.x;
    int k = i >> 8, c = i & 255;
    g_Wcat[i] = (c < 128) ? Wmu[k * 128 + c] : Wls[k * 128 + (c - 128)];
    if (i < 256) g_bcat[i] = (i < 128) ? bmu[i] : bls[i - 128];
}

// ---------------- aggregation (fp16 gather, fp32 accumulate, fp16 out) -----
// bias != null: out = relu(agg + bias); bias == null: out = agg.
__global__ void agg_h(const __half2* __restrict__ F, __half2* __restrict__ O,
                      const float* __restrict__ bias) {
    int gw = (blockIdx.x * blockDim.x + threadIdx.x) >> 5;
    if (gw >= NN) return;
    int lane = threadIdx.x & 31;

    float di = g_dinv[gw];
    float a[8];
    {
        uint4 v = *((const uint4*)(F + (size_t)gw * 128) + lane);
        const __half2* h = (const __half2*)&v;
#pragma unroll
        for (int j = 0; j < 4; j++) {
            float2 f = __half22float2(h[j]);
            a[2 * j]     = di * f.x;
            a[2 * j + 1] = di * f.y;
        }
    }
    int e = g_off[gw], eend = g_off[gw + 1];
#pragma unroll 2
    for (; e < eend; e++) {
        int s = g_csr[e];
        float w = g_dinv[s];
        uint4 v = *((const uint4*)(F + (size_t)s * 128) + lane);
        const __half2* h = (const __half2*)&v;
#pragma unroll
        for (int j = 0; j < 4; j++) {
            float2 f = __half22float2(h[j]);
            a[2 * j]     += w * f.x;
            a[2 * j + 1] += w * f.y;
        }
    }
#pragma unroll
    for (int j = 0; j < 8; j++) a[j] *= di;

    uint4 o;
    __half2* oh = (__half2*)&o;
    if (bias) {
        const float4* bp = (const float4*)bias + lane * 2;
        float4 b0 = bp[0], b1 = bp[1];
        float bb[8] = {b0.x, b0.y, b0.z, b0.w, b1.x, b1.y, b1.z, b1.w};
#pragma unroll
        for (int j = 0; j < 4; j++) {
            float x0 = fmaxf(a[2 * j]     + bb[2 * j],     0.f);
            float x1 = fmaxf(a[2 * j + 1] + bb[2 * j + 1], 0.f);
            oh[j] = __floats2half2_rn(x0, x1);
        }
    } else {
#pragma unroll
        for (int j = 0; j < 4; j++)
            oh[j] = __floats2half2_rn(a[2 * j], a[2 * j + 1]);
    }
    *((uint4*)O + (size_t)gw * 32 + lane) = o;
}

// ---------------- FP16 tensor-core GEMM (m16n8k16, fp32 accum) -------------
// C = A[M x 256] @ B[256 x 256] (+bias). Grid (ceil(M/128), 2).
// MODE 0: A fp32 (x), out fp16 T (no bias).
// MODE 1: A fp16 (G), out fp32 routed by blockIdx.y into out / out + NN*128.
__device__ __forceinline__ void mma_f16(float* d, const uint32_t* a, const uint32_t* b) {
    asm volatile(
        "mma.sync.aligned.m16n8k16.row.col.f32.f16.f16.f32 "
        "{%0,%1,%2,%3}, {%4,%5,%6,%7}, {%8,%9}, {%0,%1,%2,%3};"
        : "+f"(d[0]), "+f"(d[1]), "+f"(d[2]), "+f"(d[3])
        : "r"(a[0]), "r"(a[1]), "r"(a[2]), "r"(a[3]), "r"(b[0]), "r"(b[1]));
}

#define GBM 128
#define ASTRIDE 20    // uint32 (half2) stride; l4*20+k4 banks all distinct
#define BSTRIDE 136   // 136 % 32 == 8; k4*8+l4 banks all distinct

template <int MODE>
__global__ __launch_bounds__(256) void h16gemm_kernel(
    const void* __restrict__ Ain, const float* __restrict__ B,
    const float* __restrict__ bias, void* __restrict__ Cout, int M) {
    __shared__ uint32_t As[GBM * ASTRIDE];   // [row][k2], 32 k = 16 half2
    __shared__ uint32_t Bs[16 * BSTRIDE];    // [k2][n],   n = 0..127

    const int t = threadIdx.x;
    const int lane = t & 31;
    const int warp = t >> 5;
    const int warpM = warp >> 2;
    const int warpN = warp & 3;
    const int l4 = lane >> 2, k4 = lane & 3;
    const int rowBase = blockIdx.x * GBM;
    const int colBase = blockIdx.y * 128;
    const int mBase = warpM * 64;
    const int nBase = warpN * 32;

    // A staging coords
    const int aRow  = (MODE == 0) ? (t >> 3) : (t >> 2);       // fp32: 32 rows/chunk; fp16: 64
    const int aK2   = (MODE == 0) ? ((t & 7) << 1) : ((t & 3) << 2);
    // B staging coords
    const int bK2 = t >> 5;            // +0, +8
    const int bNc = (t & 31) << 2;

    float4 raf[4]; uint4 rah[2]; float4 rb0[2], rb1[2];
#pragma unroll
    for (int l = 0; l < 2; l++) {
        int k2 = bK2 + l * 8;
        rb0[l] = *(const float4*)(B + (size_t)(2 * k2)     * 256 + colBase + bNc);
        rb1[l] = *(const float4*)(B + (size_t)(2 * k2 + 1) * 256 + colBase + bNc);
    }
    if (MODE == 0) {
        const float* A = (const float*)Ain;
#pragma unroll
        for (int l = 0; l < 4; l++) {
            int gr = rowBase + aRow + l * 32;
            raf[l] = (gr < M) ? *(const float4*)(A + (size_t)gr * 256 + aK2 * 2)
                              : make_float4(0.f, 0.f, 0.f, 0.f);
        }
    } else {
        const __half2* A = (const __half2*)Ain;
#pragma unroll
        for (int l = 0; l < 2; l++) {
            int gr = rowBase + aRow + l * 64;
            rah[l] = (gr < M) ? *((const uint4*)(A + (size_t)gr * 128) + (aK2 >> 2))
                              : make_uint4(0u, 0u, 0u, 0u);
        }
    }

    float acc[4][4][4];
#pragma unroll
    for (int i = 0; i < 4; i++)
#pragma unroll
        for (int j = 0; j < 4; j++)
#pragma unroll
            for (int r = 0; r < 4; r++) acc[i][j][r] = 0.f;

    for (int it = 0; it < 8; it++) {
        // ---- store staged regs -> smem
        if (MODE == 0) {
#pragma unroll
            for (int l = 0; l < 4; l++) {
                uint32_t* p = &As[(aRow + l * 32) * ASTRIDE + aK2];
                p[0] = h2u(__floats2half2_rn(raf[l].x, raf[l].y));
                p[1] = h2u(__floats2half2_rn(raf[l].z, raf[l].w));
            }
        } else {
#pragma unroll
            for (int l = 0; l < 2; l++)
                *(uint4*)&As[(aRow + l * 64) * ASTRIDE + aK2] = rah[l];
        }
#pragma unroll
        for (int l = 0; l < 2; l++) {
            uint4 u;
            u.x = h2u(__floats2half2_rn(rb0[l].x, rb1[l].x));
            u.y = h2u(__floats2half2_rn(rb0[l].y, rb1[l].y));
            u.z = h2u(__floats2half2_rn(rb0[l].z, rb1[l].z));
            u.w = h2u(__floats2half2_rn(rb0[l].w, rb1[l].w));
            *(uint4*)&Bs[(bK2 + l * 8) * BSTRIDE + bNc] = u;
        }
        __syncthreads();

        // ---- prefetch next tile
        if (it < 7) {
            int k0 = (it + 1) * 32;
#pragma unroll
            for (int l = 0; l < 2; l++) {
                int k2 = (k0 >> 1) + bK2 + l * 8;
                rb0[l] = *(const float4*)(B + (size_t)(2 * k2)     * 256 + colBase + bNc);
                rb1[l] = *(const float4*)(B + (size_t)(2 * k2 + 1) * 256 + colBase + bNc);
            }
            if (MODE == 0) {
                const float* A = (const float*)Ain;
#pragma unroll
                for (int l = 0; l < 4; l++) {
                    int gr = rowBase + aRow + l * 32;
                    raf[l] = (gr < M) ? *(const float4*)(A + (size_t)gr * 256 + k0 + aK2 * 2)
                                      : make_float4(0.f, 0.f, 0.f, 0.f);
                }
            } else {
                const __half2* A = (const __half2*)Ain;
#pragma unroll
                for (int l = 0; l < 2; l++) {
                    int gr = rowBase + aRow + l * 64;
                    rah[l] = (gr < M) ? *((const uint4*)(A + (size_t)gr * 128) + ((k0 >> 1) + aK2) / 4)
                                      : make_uint4(0u, 0u, 0u, 0u);
                }
            }
        }

        // ---- compute: 2 k16 steps
#pragma unroll
        for (int ks = 0; ks < 16; ks += 8) {
            uint32_t af[4][4], bf[4][2];
#pragma unroll
            for (int mi = 0; mi < 4; mi++) {
                int r = (mBase + mi * 16 + l4) * ASTRIDE;
                af[mi][0] = As[r + ks + k4];
                af[mi][1] = As[r + 8 * ASTRIDE + ks + k4];
                af[mi][2] = As[r + ks + k4 + 4];
                af[mi][3] = As[r + 8 * ASTRIDE + ks + k4 + 4];
            }
#pragma unroll
            for (int ni = 0; ni < 4; ni++) {
                int n = nBase + ni * 8 + l4;
                bf[ni][0] = Bs[(ks + k4) * BSTRIDE + n];
                bf[ni][1] = Bs[(ks + k4 + 4) * BSTRIDE + n];
            }
#pragma unroll
            for (int mi = 0; mi < 4; mi++)
#pragma unroll
                for (int ni = 0; ni < 4; ni++)
                    mma_f16(acc[mi][ni], af[mi], bf[ni]);
        }
        __syncthreads();
    }

    // ---- epilogue
#pragma unroll
    for (int mi = 0; mi < 4; mi++) {
        int r0 = rowBase + mBase + mi * 16 + l4;
        int r1 = r0 + 8;
#pragma unroll
        for (int ni = 0; ni < 4; ni++) {
            int cl = nBase + ni * 8 + k4 * 2;
            if (MODE == 0) {
                __half2* T = (__half2*)Cout;
                int c = colBase + cl;
                if (r0 < M) T[(size_t)r0 * 128 + (c >> 1)] =
                    __floats2half2_rn(acc[mi][ni][0], acc[mi][ni][1]);
                if (r1 < M) T[(size_t)r1 * 128 + (c >> 1)] =
                    __floats2half2_rn(acc[mi][ni][2], acc[mi][ni][3]);
            } else {
                float* Co = (float*)Cout + (blockIdx.y ? (size_t)NN * 128 : 0);
                float bv0 = bias[colBase + cl];
                float bv1 = bias[colBase + cl + 1];
                if (r0 < M) {
                    float2 o; o.x = acc[mi][ni][0] + bv0; o.y = acc[mi][ni][1] + bv1;
                    *(float2*)(Co + (size_t)r0 * 128 + cl) = o;
                }
                if (r1 < M) {
                    float2 o; o.x = acc[mi][ni][2] + bv0; o.y = acc[mi][ni][3] + bv1;
                    *(float2*)(Co + (size_t)r1 * 128 + cl) = o;
                }
            }
        }
    }
}

// ---------------- launch ----------------------------------------------------
extern "C" void kernel_launch(void* const* d_in, const int* in_sizes, int n_in,
                              void* d_out, int out_size) {
    const float* x    = (const float*)d_in[0];
    const int*   ei   = (const int*)d_in[1];
    const float* W1   = (const float*)d_in[2];
    const float* b1   = (const float*)d_in[3];
    const float* Wmu  = (const float*)d_in[4];
    const float* bmu  = (const float*)d_in[5];
    const float* Wls  = (const float*)d_in[6];
    const float* bls  = (const float*)d_in[7];
    float* out = (float*)d_out;

    const int* src = ei;
    const int* dst = ei + NE;

    __half2 *pT, *pH, *pG; float *pWcat, *pbcat;
    cudaGetSymbolAddress((void**)&pT, g_T);
    cudaGetSymbolAddress((void**)&pH, g_H);
    cudaGetSymbolAddress((void**)&pG, g_G);
    cudaGetSymbolAddress((void**)&pWcat, g_Wcat);
    cudaGetSymbolAddress((void**)&pbcat, g_bcat);

    init_kernel<<<(NN + 255) / 256, 256>>>();
    count_kernel<<<(NE + 255) / 256, 256>>>(dst);
    wcat_kernel<<<256, 256>>>(Wmu, Wls, bmu, bls);
    blocksum_kernel<<<NB, 256>>>();
    bscan_kernel<<<1, 256>>>();
    offsets_kernel<<<NB, 256>>>();
    fill_kernel<<<(NE + 255) / 256, 256>>>(src, dst);

    dim3 ggrid((NN + GBM - 1) / GBM, 2);
    // T = x @ W1  (fp16 out)
    h16gemm_kernel<0><<<ggrid, 256>>>(x, W1, nullptr, pT, NN);
    // H = relu(Â T + b1)
    agg_h<<<(NN * 32 + 255) / 256, 256>>>(pT, pH, b1);
    // G = Â H
    agg_h<<<(NN * 32 + 255) / 256, 256>>>(pH, pG, nullptr);
    // [mu | ls] = G @ [Wmu | Wls] + [bmu | bls]
    h16gemm_kernel<1><<<ggrid, 256>>>(pG, pWcat, pbcat, out, NN);
}